// round 1
// baseline (speedup 1.0000x reference)
#include <cuda_runtime.h>

// Forward_Model_27616639714079: batched 12x12 complex-DFT magnitude, two passes
// (accurate scale=255 folded away; approx weights = round(w*65535)/65536),
// output = acc + (apx - acc) elementwise (fp32, matches reference semantics).
//
// Strategy: pack 2 tiles per thread lane as f32x2 and use Blackwell packed
// fma.rn.f32x2 (2 FMA per fma-pipe issue). Thread = (tile-pair, output row r).
// Stage A (T = W@x) keeps the 24 dup'd weights of row r in registers and
// streams x columns from shared (conflict-free via 145-word pitch).
// Stage B streams broadcast dup'd weights from shared, 3-mult complex trick.

#define IMGN 12
typedef unsigned long long u64;

__device__ __forceinline__ u64 pk2(float lo, float hi) {
    u64 r; asm("mov.b64 %0,{%1,%2};" : "=l"(r) : "f"(lo), "f"(hi)); return r;
}
__device__ __forceinline__ void upk2(u64 v, float& lo, float& hi) {
    asm("mov.b64 {%0,%1},%2;" : "=f"(lo), "=f"(hi) : "l"(v));
}
__device__ __forceinline__ u64 fma2(u64 a, u64 b, u64 c) {
    u64 d; asm("fma.rn.f32x2 %0,%1,%2,%3;" : "=l"(d) : "l"(a), "l"(b), "l"(c)); return d;
}
__device__ __forceinline__ u64 add2(u64 a, u64 b) {
    u64 d; asm("add.rn.f32x2 %0,%1,%2;" : "=l"(d) : "l"(a), "l"(b)); return d;
}
__device__ __forceinline__ u64 mul2(u64 a, u64 b) {
    u64 d; asm("mul.rn.f32x2 %0,%1,%2;" : "=l"(d) : "l"(a), "l"(b)); return d;
}
// negate both packed floats via sign-bit xor (alu pipe, keeps fma pipe free)
__device__ __forceinline__ u64 neg2(u64 a) { return a ^ 0x8000000080000000ULL; }
__device__ __forceinline__ float sqrt_ap(float x) {
    float r; asm("sqrt.approx.f32 %0,%1;" : "=f"(r) : "f"(x)); return r;
}

// block: 192 threads = 16 tile-pairs (32 tiles) x 12 rows
__global__ void __launch_bounds__(192, 2)
dft_mag_kernel(const float* __restrict__ x,
               const float* __restrict__ wr,
               const float* __restrict__ wi,
               float* __restrict__ out, int size)
{
    // [pass][{real,imag,real+imag}][k*12+c], each weight duplicated into f32x2
    __shared__ u64 sW[2][3][144];
    // [pair][j*12+c] ; pitch 145 (8B words): 145 mod 16 == 1 -> conflict-free
    __shared__ u64 sX[16][145];

    const int t = threadIdx.x;

    // ---- weight prep (144 threads) ----
    if (t < 144) {
        float a = wr[t], b = wi[t];
        sW[0][0][t] = pk2(a, a);
        sW[0][1][t] = pk2(b, b);
        float s = a + b;
        sW[0][2][t] = pk2(s, s);
        // approx pass: round-half-even like jnp.round; /65536 exact (pow2)
        float qa = rintf(a * 65535.0f) * (1.0f / 65536.0f);
        float qb = rintf(b * 65535.0f) * (1.0f / 65536.0f);
        sW[1][0][t] = pk2(qa, qa);
        sW[1][1][t] = pk2(qb, qb);
        float qs = qa + qb;
        sW[1][2][t] = pk2(qs, qs);
    }

    // ---- load 32 tiles (4608 floats = 1152 float4) into paired shared layout ----
    const long nfloat = (long)size * 144;
    const long base = (long)blockIdx.x * 32 * 144;   // float index
    const float4* in4 = reinterpret_cast<const float4*>(x + base);
#pragma unroll
    for (int i = 0; i < 6; i++) {
        int e4 = i * 192 + t;                 // 0..1151
        if (base + (long)e4 * 4 < nfloat) {
            float4 v = in4[e4];
            int e = e4 * 4;                    // 144 % 4 == 0 -> same tile
            int item = e / 144;                // 0..31
            int jc = e % 144;
            float* dst = reinterpret_cast<float*>(&sX[item >> 1][jc]) + (item & 1);
            dst[0] = v.x; dst[2] = v.y; dst[4] = v.z; dst[6] = v.w;
        }
    }
    __syncthreads();

    const int r  = t / 16;     // output row 0..11
    const int pr = t % 16;     // tile pair 0..15
    const u64* xp = sX[pr];

    u64 mag0[12];

#pragma unroll
    for (int P = 0; P < 2; P++) {
        const u64* WR = sW[P][0];
        const u64* WI = sW[P][1];
        const u64* WS = sW[P][2];

        // row-r weights, register resident (already dup'd)
        u64 wra[12], wia[12];
#pragma unroll
        for (int j = 0; j < 12; j++) {
            wra[j] = WR[r * 12 + j];
            wia[j] = WI[r * 12 + j];
        }

        // stage A: rt[c] = sum_j wr[r,j]*x[j,c] ; it likewise
        u64 rt[12], it[12];
#pragma unroll
        for (int c = 0; c < 12; c++) {
            u64 a = 0, b = 0;
#pragma unroll
            for (int j = 0; j < 12; j++) {
                u64 xv = xp[j * 12 + c];
                a = fma2(wra[j], xv, a);
                b = fma2(wia[j], xv, b);
            }
            rt[c] = a; it[c] = b;
        }

        u64 st[12];
#pragma unroll
        for (int k = 0; k < 12; k++) st[k] = add2(rt[k], it[k]);

        // stage B (3-mult complex): P1=rt@wr, P2=it@wi, P3=(rt+it)@(wr+wi)
        // ro = P1-P2, io = P3-P1-P2 ; out = sqrt(ro^2+io^2)
#pragma unroll
        for (int c = 0; c < 12; c++) {
            u64 p1 = 0, p2 = 0, p3 = 0;
#pragma unroll
            for (int k = 0; k < 12; k++) {
                p1 = fma2(rt[k], WR[k * 12 + c], p1);
                p2 = fma2(it[k], WI[k * 12 + c], p2);
                p3 = fma2(st[k], WS[k * 12 + c], p3);
            }
            u64 ro = add2(p1, neg2(p2));
            u64 io = add2(p3, neg2(add2(p1, p2)));
            u64 m  = fma2(ro, ro, mul2(io, io));
            float lo, hi; upk2(m, lo, hi);
            u64 mg = pk2(sqrt_ap(lo), sqrt_ap(hi));
            if (P == 0) {
                mag0[c] = mg;                                // accurate pass
            } else {
                // out = acc + (apx - acc)  (same fp order as reference)
                mag0[c] = add2(mag0[c], add2(mg, neg2(mag0[c])));
            }
        }
    }

    // ---- store: two tile rows (lo/hi lanes), 3x float4 each ----
    long item0 = (long)blockIdx.x * 32 + 2 * pr;
    if (item0 + 1 < (long)size) {
        float lo[12], hi[12];
#pragma unroll
        for (int c = 0; c < 12; c++) upk2(mag0[c], lo[c], hi[c]);
        float4* o0 = reinterpret_cast<float4*>(out + item0 * 144 + r * 12);
        float4* o1 = reinterpret_cast<float4*>(out + (item0 + 1) * 144 + r * 12);
        o0[0] = make_float4(lo[0], lo[1], lo[2],  lo[3]);
        o0[1] = make_float4(lo[4], lo[5], lo[6],  lo[7]);
        o0[2] = make_float4(lo[8], lo[9], lo[10], lo[11]);
        o1[0] = make_float4(hi[0], hi[1], hi[2],  hi[3]);
        o1[1] = make_float4(hi[4], hi[5], hi[6],  hi[7]);
        o1[2] = make_float4(hi[8], hi[9], hi[10], hi[11]);
    } else if (item0 < (long)size) {       // odd tail (not hit at size=100000)
        float lo[12], hi[12];
#pragma unroll
        for (int c = 0; c < 12; c++) upk2(mag0[c], lo[c], hi[c]);
        float* o0 = out + item0 * 144 + r * 12;
#pragma unroll
        for (int c = 0; c < 12; c++) o0[c] = lo[c];
    }
}

extern "C" void kernel_launch(void* const* d_in, const int* in_sizes, int n_in,
                              void* d_out, int out_size)
{
    const float* x  = (const float*)d_in[0];
    const float* wr = (const float*)d_in[1];
    const float* wi = (const float*)d_in[2];
    float* out = (float*)d_out;

    int size = in_sizes[0] / 144;              // number of 12x12 tiles (100000)
    int blocks = (size + 31) / 32;             // 32 tiles per block -> 3125
    dft_mag_kernel<<<blocks, 192>>>(x, wr, wi, out, size);
}

// round 2
// speedup vs baseline: 2.7733x; 2.7733x over previous
#include <cuda_runtime.h>

// Batched 12x12 complex-DFT magnitude. Reference output = acc + (apx - acc)
// which equals the approx pass to ~2 ulp, so we compute ONLY the approx pass
// (weights quantized round(w*65535)/65536, /65536 folded into weights exactly).
//
// f32x2-packed: 2 tiles per lane, fma.rn.f32x2 everywhere.
// Thread = (tile-pair pr 0..15, output row r 0..11); 192 threads, 32 tiles/block.
// Stage A: j-outer, x row contiguous (LDS.128 x2-u64), one 16B weight broadcast/j.
// Stage B: transposed interleaved weights, one broadcast LDS.128 per (c,k).

typedef unsigned long long u64;

__device__ __forceinline__ u64 pk2(float lo, float hi) {
    u64 r; asm("mov.b64 %0,{%1,%2};" : "=l"(r) : "f"(lo), "f"(hi)); return r;
}
__device__ __forceinline__ void upk2(u64 v, float& lo, float& hi) {
    asm("mov.b64 {%0,%1},%2;" : "=f"(lo), "=f"(hi) : "l"(v));
}
__device__ __forceinline__ u64 fma2(u64 a, u64 b, u64 c) {
    u64 d; asm("fma.rn.f32x2 %0,%1,%2,%3;" : "=l"(d) : "l"(a), "l"(b), "l"(c)); return d;
}
__device__ __forceinline__ u64 add2(u64 a, u64 b) {
    u64 d; asm("add.rn.f32x2 %0,%1,%2;" : "=l"(d) : "l"(a), "l"(b)); return d;
}
__device__ __forceinline__ u64 mul2(u64 a, u64 b) {
    u64 d; asm("mul.rn.f32x2 %0,%1,%2;" : "=l"(d) : "l"(a), "l"(b)); return d;
}
__device__ __forceinline__ u64 neg2(u64 a) { return a ^ 0x8000000080000000ULL; }
__device__ __forceinline__ float sqrt_ap(float x) {
    float r; asm("sqrt.approx.f32 %0,%1;" : "=f"(r) : "f"(x)); return r;
}

#define PITCH 146   // u64 pitch per tile-pair row: even (16B-aligned rows)

__global__ void __launch_bounds__(192, 3)
dft_mag_kernel(const float* __restrict__ x,
               const float* __restrict__ wr,
               const float* __restrict__ wi,
               float* __restrict__ out, int size)
{
    // Stage A weights: sWA[r*12+j] = {dup(qwr[r][j]), dup(qwi[r][j])}
    __shared__ ulonglong2 sWA[144];
    // Stage B weights transposed: sWB[c*12+k] = {dup(qwr[k][c]), dup(qwi[k][c])}
    __shared__ ulonglong2 sWB[144];
    // x tile pairs: sX[pr][j*12+c] packed f32x2 (lo=tile 2*pr, hi=tile 2*pr+1)
    __shared__ u64 sX[16][PITCH];

    const int t = threadIdx.x;

    // ---- weight prep (144 threads); quantize + fold /65536 (exact pow2) ----
    if (t < 144) {
        float qa = rintf(wr[t] * 65535.0f) * (1.0f / 65536.0f);
        float qb = rintf(wi[t] * 65535.0f) * (1.0f / 65536.0f);
        ulonglong2 w; w.x = pk2(qa, qa); w.y = pk2(qb, qb);
        sWA[t] = w;                                   // [r*12+j] = [t]
        sWB[(t % 12) * 12 + (t / 12)] = w;            // transpose: [c*12+k]
    }

    // ---- load 32 tiles (1152 float4) into paired-lane shared layout ----
    const long nfloat = (long)size * 144;
    const long base = (long)blockIdx.x * 32 * 144;
    const float4* in4 = reinterpret_cast<const float4*>(x + base);
#pragma unroll
    for (int i = 0; i < 6; i++) {
        int e4 = i * 192 + t;                 // 0..1151
        if (base + (long)e4 * 4 < nfloat) {
            float4 v = in4[e4];
            int e = e4 * 4;
            int item = e / 144;               // 0..31  (144%4==0 -> same tile)
            int jc = e % 144;
            float* dst = reinterpret_cast<float*>(&sX[item >> 1][jc]) + (item & 1);
            dst[0] = v.x; dst[2] = v.y; dst[4] = v.z; dst[6] = v.w;
        }
    }
    __syncthreads();

    const int r  = t / 16;                    // output row 0..11
    const int pr = t % 16;                    // tile pair 0..15
    const u64* xp = sX[pr];

    // ---- stage A: rt[c] = sum_j w[r][j]*x[j][c] (j-outer, x row contiguous) ----
    u64 rt[12], it[12];
#pragma unroll
    for (int c = 0; c < 12; c++) { rt[c] = 0; it[c] = 0; }
#pragma unroll
    for (int j = 0; j < 12; j++) {
        ulonglong2 w = sWA[r * 12 + j];       // broadcast (2 addrs per warp)
        const ulonglong2* xr = reinterpret_cast<const ulonglong2*>(xp + j * 12);
        ulonglong2 x0 = xr[0], x1 = xr[1], x2 = xr[2],
                   x3 = xr[3], x4 = xr[4], x5 = xr[5];
        u64 xv[12] = { x0.x, x0.y, x1.x, x1.y, x2.x, x2.y,
                       x3.x, x3.y, x4.x, x4.y, x5.x, x5.y };
#pragma unroll
        for (int c = 0; c < 12; c++) {
            rt[c] = fma2(w.x, xv[c], rt[c]);
            it[c] = fma2(w.y, xv[c], it[c]);
        }
    }

    // ---- stage B: ro = rt@Wr - it@Wi ; io = rt@Wi + it@Wr ; |.| ----
    float lo[12], hi[12];
#pragma unroll
    for (int c = 0; c < 12; c++) {
        u64 p1 = 0, p2 = 0, p3 = 0, p4 = 0;
#pragma unroll
        for (int k = 0; k < 12; k++) {
            ulonglong2 w = sWB[c * 12 + k];   // full-warp broadcast, 1 phase
            p1 = fma2(rt[k], w.x, p1);
            p2 = fma2(it[k], w.y, p2);
            p3 = fma2(rt[k], w.y, p3);
            p4 = fma2(it[k], w.x, p4);
        }
        u64 ro = add2(p1, neg2(p2));
        u64 io = add2(p3, p4);
        u64 m  = fma2(ro, ro, mul2(io, io));
        float mlo, mhi; upk2(m, mlo, mhi);
        lo[c] = sqrt_ap(mlo);
        hi[c] = sqrt_ap(mhi);
    }

    // ---- store: two tile rows (lo/hi lanes), 3x float4 each ----
    long item0 = (long)blockIdx.x * 32 + 2 * pr;
    if (item0 + 1 < (long)size) {
        float4* o0 = reinterpret_cast<float4*>(out + item0 * 144 + r * 12);
        float4* o1 = reinterpret_cast<float4*>(out + (item0 + 1) * 144 + r * 12);
        o0[0] = make_float4(lo[0], lo[1], lo[2],  lo[3]);
        o0[1] = make_float4(lo[4], lo[5], lo[6],  lo[7]);
        o0[2] = make_float4(lo[8], lo[9], lo[10], lo[11]);
        o1[0] = make_float4(hi[0], hi[1], hi[2],  hi[3]);
        o1[1] = make_float4(hi[4], hi[5], hi[6],  hi[7]);
        o1[2] = make_float4(hi[8], hi[9], hi[10], hi[11]);
    } else if (item0 < (long)size) {          // odd tail (unused at size=100000)
        float* o0 = out + item0 * 144 + r * 12;
#pragma unroll
        for (int c = 0; c < 12; c++) o0[c] = lo[c];
    }
}

extern "C" void kernel_launch(void* const* d_in, const int* in_sizes, int n_in,
                              void* d_out, int out_size)
{
    const float* x  = (const float*)d_in[0];
    const float* wr = (const float*)d_in[1];
    const float* wi = (const float*)d_in[2];
    float* out = (float*)d_out;

    int size = in_sizes[0] / 144;              // tiles (100000)
    int blocks = (size + 31) / 32;             // 3125
    dft_mag_kernel<<<blocks, 192>>>(x, wr, wi, out, size);
}

// round 3
// speedup vs baseline: 3.6189x; 1.3049x over previous
#include <cuda_runtime.h>

// Batched 12x12 complex-DFT magnitude, approx pass only (== reference output
// to ~2 ulp since out = acc + (apx - acc) elementwise in fp32).
// Weights: round(w*65535)/65536, /65536 folded exactly (pow2).
//
// f32x2-packed: 2 tiles per lane. Thread t -> (pr = t/12 tile-pair, r = t%12
// output row). A warp spans <=3 pr values, so stage-A x-row LDS.128s are
// ~3-address near-broadcasts (1 wavefront instead of 4). Stage-B weights are
// full-warp broadcasts. Input staged via pair-packed STS.128 (conflict-free).

typedef unsigned long long u64;

__device__ __forceinline__ u64 pk2(float lo, float hi) {
    u64 r; asm("mov.b64 %0,{%1,%2};" : "=l"(r) : "f"(lo), "f"(hi)); return r;
}
__device__ __forceinline__ void upk2(u64 v, float& lo, float& hi) {
    asm("mov.b64 {%0,%1},%2;" : "=f"(lo), "=f"(hi) : "l"(v));
}
__device__ __forceinline__ u64 fma2(u64 a, u64 b, u64 c) {
    u64 d; asm("fma.rn.f32x2 %0,%1,%2,%3;" : "=l"(d) : "l"(a), "l"(b), "l"(c)); return d;
}
__device__ __forceinline__ u64 add2(u64 a, u64 b) {
    u64 d; asm("add.rn.f32x2 %0,%1,%2;" : "=l"(d) : "l"(a), "l"(b)); return d;
}
__device__ __forceinline__ u64 mul2(u64 a, u64 b) {
    u64 d; asm("mul.rn.f32x2 %0,%1,%2;" : "=l"(d) : "l"(a), "l"(b)); return d;
}
__device__ __forceinline__ u64 neg2(u64 a) { return a ^ 0x8000000080000000ULL; }
__device__ __forceinline__ float sqrt_ap(float x) {
    float r; asm("sqrt.approx.f32 %0,%1;" : "=f"(r) : "f"(x)); return r;
}

#define PITCH 146   // u64 pitch: even (16B rows), 146*8 mod 128 = 16 -> pr-rows
                    // land on distinct 16B bank slots for 8 consecutive prs

__global__ void __launch_bounds__(192, 3)
dft_mag_kernel(const float* __restrict__ x,
               const float* __restrict__ wr,
               const float* __restrict__ wi,
               float* __restrict__ out, int size)
{
    __shared__ ulonglong2 sWA[144];   // [r*12+j] = {dup(qwr), dup(qwi)}
    __shared__ ulonglong2 sWB[144];   // transposed: [c*12+k]
    __shared__ u64 sX[16][PITCH];     // [pair][j*12+c] f32x2 (lo=2p, hi=2p+1)

    const int t = threadIdx.x;

    // ---- weight prep (144 threads) ----
    if (t < 144) {
        float qa = rintf(wr[t] * 65535.0f) * (1.0f / 65536.0f);
        float qb = rintf(wi[t] * 65535.0f) * (1.0f / 65536.0f);
        ulonglong2 w; w.x = pk2(qa, qa); w.y = pk2(qb, qb);
        sWA[t] = w;
        sWB[(t % 12) * 12 + (t / 12)] = w;
    }

    // ---- stage-in 32 tiles: 576 pair-sets, 3 per thread ----
    // pair-set p: pair = p/36, q = p%36; loads float4 q of tile 2*pair and
    // 2*pair+1, packs lanes, stores 32B contiguous (2x STS.128, no conflicts).
    const long base4 = (long)blockIdx.x * 32 * 36;     // float4 index
    const long n4 = ((long)size * 144) >> 2;
    const float4* in4 = reinterpret_cast<const float4*>(x);
#pragma unroll
    for (int s = 0; s < 3; s++) {
        int p = s * 192 + t;              // 0..575
        int pair = p / 36, q = p % 36;
        long i0 = base4 + (long)pair * 72 + q;
        if (i0 + 36 < n4) {
            float4 v0 = in4[i0];
            float4 v1 = in4[i0 + 36];
            ulonglong2* dst = reinterpret_cast<ulonglong2*>(&sX[pair][q * 4]);
            ulonglong2 d0, d1;
            d0.x = pk2(v0.x, v1.x); d0.y = pk2(v0.y, v1.y);
            d1.x = pk2(v0.z, v1.z); d1.y = pk2(v0.w, v1.w);
            dst[0] = d0; dst[1] = d1;
        }
    }
    __syncthreads();

    const int pr = t / 12;     // tile pair 0..15 (warp spans <=3 values)
    const int r  = t % 12;     // output row
    const u64* xp = sX[pr];

    // ---- stage A: rt[c] = sum_j w[r][j] * x[j][c] ----
    u64 rt[12], it[12];
#pragma unroll
    for (int c = 0; c < 12; c++) { rt[c] = 0; it[c] = 0; }
#pragma unroll
    for (int j = 0; j < 12; j++) {
        ulonglong2 w = sWA[r * 12 + j];                 // 12 addrs/warp
        const ulonglong2* xr = reinterpret_cast<const ulonglong2*>(xp + j * 12);
        ulonglong2 x0 = xr[0], x1 = xr[1], x2 = xr[2],
                   x3 = xr[3], x4 = xr[4], x5 = xr[5];  // ~3 addrs/warp each
        u64 xv[12] = { x0.x, x0.y, x1.x, x1.y, x2.x, x2.y,
                       x3.x, x3.y, x4.x, x4.y, x5.x, x5.y };
#pragma unroll
        for (int c = 0; c < 12; c++) {
            rt[c] = fma2(w.x, xv[c], rt[c]);
            it[c] = fma2(w.y, xv[c], it[c]);
        }
    }

    // ---- stage B: ro = rt@Wr - it@Wi ; io = rt@Wi + it@Wr ; magnitude ----
    float lo[12], hi[12];
#pragma unroll
    for (int c = 0; c < 12; c++) {
        u64 p1 = 0, p2 = 0, p3 = 0, p4 = 0;
#pragma unroll
        for (int k = 0; k < 12; k++) {
            ulonglong2 w = sWB[c * 12 + k];             // full-warp broadcast
            p1 = fma2(rt[k], w.x, p1);
            p2 = fma2(it[k], w.y, p2);
            p3 = fma2(rt[k], w.y, p3);
            p4 = fma2(it[k], w.x, p4);
        }
        u64 ro = add2(p1, neg2(p2));
        u64 io = add2(p3, p4);
        u64 m  = fma2(ro, ro, mul2(io, io));
        float mlo, mhi; upk2(m, mlo, mhi);
        lo[c] = sqrt_ap(mlo);
        hi[c] = sqrt_ap(mhi);
    }

    // ---- store: row r of tiles 2pr, 2pr+1 ----
    long item0 = (long)blockIdx.x * 32 + 2 * pr;
    if (item0 + 1 < (long)size) {
        float4* o0 = reinterpret_cast<float4*>(out + item0 * 144 + r * 12);
        float4* o1 = reinterpret_cast<float4*>(out + (item0 + 1) * 144 + r * 12);
        o0[0] = make_float4(lo[0], lo[1], lo[2],  lo[3]);
        o0[1] = make_float4(lo[4], lo[5], lo[6],  lo[7]);
        o0[2] = make_float4(lo[8], lo[9], lo[10], lo[11]);
        o1[0] = make_float4(hi[0], hi[1], hi[2],  hi[3]);
        o1[1] = make_float4(hi[4], hi[5], hi[6],  hi[7]);
        o1[2] = make_float4(hi[8], hi[9], hi[10], hi[11]);
    } else if (item0 < (long)size) {       // tail (unused at size=100000)
        float* o0 = out + item0 * 144 + r * 12;
#pragma unroll
        for (int c = 0; c < 12; c++) o0[c] = lo[c];
    }
}

extern "C" void kernel_launch(void* const* d_in, const int* in_sizes, int n_in,
                              void* d_out, int out_size)
{
    const float* x  = (const float*)d_in[0];
    const float* wr = (const float*)d_in[1];
    const float* wi = (const float*)d_in[2];
    float* out = (float*)d_out;

    int size = in_sizes[0] / 144;              // tiles (100000)
    int blocks = (size + 31) / 32;             // 3125 exactly
    dft_mag_kernel<<<blocks, 192>>>(x, wr, wi, out, size);
}

// round 4
// speedup vs baseline: 4.1548x; 1.1481x over previous
#include <cuda_runtime.h>

// Batched 12x12 complex-DFT magnitude, approx pass only (== reference to ~2ulp).
// f32x2-packed (2 tiles/lane). Thread t -> (pr=t/12 tile-pair, r=t%12 row).
// Stage-B weights exploit DFT structure: W[k][c] depends only on m=(k*c)%12,
// so 12 register-resident dup'd pairs with COMPILE-TIME indices -> zero LDS
// in the stage-B inner loops.

typedef unsigned long long u64;

__device__ __forceinline__ u64 pk2(float lo, float hi) {
    u64 r; asm("mov.b64 %0,{%1,%2};" : "=l"(r) : "f"(lo), "f"(hi)); return r;
}
__device__ __forceinline__ void upk2(u64 v, float& lo, float& hi) {
    asm("mov.b64 {%0,%1},%2;" : "=f"(lo), "=f"(hi) : "l"(v));
}
__device__ __forceinline__ u64 fma2(u64 a, u64 b, u64 c) {
    u64 d; asm("fma.rn.f32x2 %0,%1,%2,%3;" : "=l"(d) : "l"(a), "l"(b), "l"(c)); return d;
}
__device__ __forceinline__ u64 add2(u64 a, u64 b) {
    u64 d; asm("add.rn.f32x2 %0,%1,%2;" : "=l"(d) : "l"(a), "l"(b)); return d;
}
__device__ __forceinline__ u64 mul2(u64 a, u64 b) {
    u64 d; asm("mul.rn.f32x2 %0,%1,%2;" : "=l"(d) : "l"(a), "l"(b)); return d;
}
__device__ __forceinline__ u64 neg2(u64 a) { return a ^ 0x8000000080000000ULL; }
__device__ __forceinline__ float sqrt_ap(float x) {
    float r; asm("sqrt.approx.f32 %0,%1;" : "=f"(r) : "f"(x)); return r;
}

#define PITCH 146   // u64 pitch (even -> 16B-aligned rows, bank-spread)
#define NPAIR 8     // tile pairs per block (16 tiles)
#define NTHR  96    // NPAIR*12

__global__ void __launch_bounds__(NTHR, 5)
dft_mag_kernel(const float* __restrict__ x,
               const float* __restrict__ wr,
               const float* __restrict__ wi,
               float* __restrict__ out, int size)
{
    __shared__ ulonglong2 sWA[144];    // exact per-entry weights [r*12+j]
    __shared__ ulonglong2 sLUT[12];    // 12 distinct weights, LUT[m], m=jk%12
    __shared__ u64 sX[NPAIR][PITCH];   // [pair][j*12+c] f32x2 (lo=2p, hi=2p+1)

    const int t = threadIdx.x;

    // ---- weight prep ----
    for (int i = t; i < 144; i += NTHR) {
        float qa = rintf(wr[i] * 65535.0f) * (1.0f / 65536.0f);
        float qb = rintf(wi[i] * 65535.0f) * (1.0f / 65536.0f);
        ulonglong2 w; w.x = pk2(qa, qa); w.y = pk2(qb, qb);
        sWA[i] = w;
    }
    if (t < 12) {
        // representative for m: row 1, col m  (j*k = m exactly)
        float qa = rintf(wr[12 + t] * 65535.0f) * (1.0f / 65536.0f);
        float qb = rintf(wi[12 + t] * 65535.0f) * (1.0f / 65536.0f);
        ulonglong2 w; w.x = pk2(qa, qa); w.y = pk2(qb, qb);
        sLUT[t] = w;
    }

    // ---- stage-in 16 tiles: 288 pair-sets, 3 per thread ----
    const long base4 = (long)blockIdx.x * NPAIR * 72;   // float4 index
    const long n4 = ((long)size * 144) >> 2;
    const float4* in4 = reinterpret_cast<const float4*>(x);
#pragma unroll
    for (int s = 0; s < 3; s++) {
        int p = s * NTHR + t;             // 0..287
        int pair = p / 36, q = p % 36;
        long i0 = base4 + (long)pair * 72 + q;
        if (i0 + 36 < n4) {
            float4 v0 = in4[i0];
            float4 v1 = in4[i0 + 36];
            ulonglong2* dst = reinterpret_cast<ulonglong2*>(&sX[pair][q * 4]);
            ulonglong2 d0, d1;
            d0.x = pk2(v0.x, v1.x); d0.y = pk2(v0.y, v1.y);
            d1.x = pk2(v0.z, v1.z); d1.y = pk2(v0.w, v1.w);
            dst[0] = d0; dst[1] = d1;
        }
    }
    __syncthreads();

    const int pr = t / 12;     // warp spans <=3 pr values
    const int r  = t % 12;
    const u64* xp = sX[pr];

    // ---- stage A: rt[c] = sum_j w[r][j]*x[j][c] (j=0 peeled to mul) ----
    u64 rt[12], it[12];
    {
        ulonglong2 w0 = sWA[r * 12];
        const ulonglong2* xr = reinterpret_cast<const ulonglong2*>(xp);
        ulonglong2 x0 = xr[0], x1 = xr[1], x2 = xr[2],
                   x3 = xr[3], x4 = xr[4], x5 = xr[5];
        u64 xv[12] = { x0.x, x0.y, x1.x, x1.y, x2.x, x2.y,
                       x3.x, x3.y, x4.x, x4.y, x5.x, x5.y };
#pragma unroll
        for (int c = 0; c < 12; c++) {
            rt[c] = mul2(w0.x, xv[c]);
            it[c] = mul2(w0.y, xv[c]);
        }
    }
#pragma unroll
    for (int j = 1; j < 12; j++) {
        ulonglong2 w = sWA[r * 12 + j];
        const ulonglong2* xr = reinterpret_cast<const ulonglong2*>(xp + j * 12);
        ulonglong2 x0 = xr[0], x1 = xr[1], x2 = xr[2],
                   x3 = xr[3], x4 = xr[4], x5 = xr[5];
        u64 xv[12] = { x0.x, x0.y, x1.x, x1.y, x2.x, x2.y,
                       x3.x, x3.y, x4.x, x4.y, x5.x, x5.y };
#pragma unroll
        for (int c = 0; c < 12; c++) {
            rt[c] = fma2(w.x, xv[c], rt[c]);
            it[c] = fma2(w.y, xv[c], it[c]);
        }
    }

    // ---- load 12 distinct stage-B weights into registers ----
    u64 wre[12], wim[12];
#pragma unroll
    for (int m = 0; m < 12; m++) {
        ulonglong2 w = sLUT[m];            // full-warp broadcast
        wre[m] = w.x; wim[m] = w.y;
    }

    // ---- stage B: per 4-column group, compile-time weight indices ----
    float* ob = out + ((long)blockIdx.x * NPAIR * 2 + 2 * pr) * 144 + r * 12;
    long item0 = (long)blockIdx.x * NPAIR * 2 + 2 * pr;
    bool full = (item0 + 1 < (long)size);

#pragma unroll
    for (int g = 0; g < 3; g++) {
        float lo4[4], hi4[4];
#pragma unroll
        for (int cc = 0; cc < 4; cc++) {
            const int c = g * 4 + cc;
            u64 p1 = mul2(rt[0], wre[0]);
            u64 p2 = mul2(it[0], wim[0]);
            u64 p3 = mul2(rt[0], wim[0]);
            u64 p4 = mul2(it[0], wre[0]);
#pragma unroll
            for (int k = 1; k < 12; k++) {
                const int m = (k * c) % 12;        // compile-time
                p1 = fma2(rt[k], wre[m], p1);
                p2 = fma2(it[k], wim[m], p2);
                p3 = fma2(rt[k], wim[m], p3);
                p4 = fma2(it[k], wre[m], p4);
            }
            u64 ro = add2(p1, neg2(p2));
            u64 io = add2(p3, p4);
            u64 mg = fma2(ro, ro, mul2(io, io));
            float mlo, mhi; upk2(mg, mlo, mhi);
            lo4[cc] = sqrt_ap(mlo);
            hi4[cc] = sqrt_ap(mhi);
        }
        if (full) {
            reinterpret_cast<float4*>(ob)[g] =
                make_float4(lo4[0], lo4[1], lo4[2], lo4[3]);
            reinterpret_cast<float4*>(ob + 144)[g] =
                make_float4(hi4[0], hi4[1], hi4[2], hi4[3]);
        } else if (item0 < (long)size) {   // odd tail (unused at size=100000)
#pragma unroll
            for (int cc = 0; cc < 4; cc++) ob[g * 4 + cc] = lo4[cc];
        }
    }
}

extern "C" void kernel_launch(void* const* d_in, const int* in_sizes, int n_in,
                              void* d_out, int out_size)
{
    const float* x  = (const float*)d_in[0];
    const float* wr = (const float*)d_in[1];
    const float* wi = (const float*)d_in[2];
    float* out = (float*)d_out;

    int size = in_sizes[0] / 144;                      // tiles (100000)
    int blocks = (size + NPAIR * 2 - 1) / (NPAIR * 2); // 6250 exactly
    dft_mag_kernel<<<blocks, NTHR>>>(x, wr, wi, out, size);
}

// round 5
// speedup vs baseline: 4.5381x; 1.0922x over previous
#include <cuda_runtime.h>

// Batched 12x12 complex-DFT magnitude, approx pass only.
// R5: Hermitian symmetry (real input): |F[12-r,12-c]| = |F[r,c]| -> compute
// rows 0..6 only, mirror rows 7..11 with reversed columns. Stage-B real
// weights are even in m (exact post-quant) -> k/(12-k) pairing shrinks the
// wre dot products 12->7 terms. f32x2 packing: 2 tiles per lane.

typedef unsigned long long u64;

__device__ __forceinline__ u64 pk2(float lo, float hi) {
    u64 r; asm("mov.b64 %0,{%1,%2};" : "=l"(r) : "f"(lo), "f"(hi)); return r;
}
__device__ __forceinline__ void upk2(u64 v, float& lo, float& hi) {
    asm("mov.b64 {%0,%1},%2;" : "=f"(lo), "=f"(hi) : "l"(v));
}
__device__ __forceinline__ u64 fma2(u64 a, u64 b, u64 c) {
    u64 d; asm("fma.rn.f32x2 %0,%1,%2,%3;" : "=l"(d) : "l"(a), "l"(b), "l"(c)); return d;
}
__device__ __forceinline__ u64 add2(u64 a, u64 b) {
    u64 d; asm("add.rn.f32x2 %0,%1,%2;" : "=l"(d) : "l"(a), "l"(b)); return d;
}
__device__ __forceinline__ u64 mul2(u64 a, u64 b) {
    u64 d; asm("mul.rn.f32x2 %0,%1,%2;" : "=l"(d) : "l"(a), "l"(b)); return d;
}
__device__ __forceinline__ u64 neg2(u64 a) { return a ^ 0x8000000080000000ULL; }
__device__ __forceinline__ float sqrt_ap(float x) {
    float r; asm("sqrt.approx.f32 %0,%1;" : "=f"(r) : "f"(x)); return r;
}

#define PITCH 146    // u64 pitch (even -> 16B rows; pr step = 16B bank shift)
#define NPAIR 32     // tile pairs per block (64 tiles)
#define NROW  7      // rows 0..6 computed; 7..11 mirrored
#define NTHR  224    // NPAIR * NROW = 7 warps

__global__ void __launch_bounds__(NTHR, 2)
dft_mag_kernel(const float* __restrict__ x,
               const float* __restrict__ wr,
               const float* __restrict__ wi,
               float* __restrict__ out, int size)
{
    __shared__ ulonglong2 sWA[144];    // stage-A weights [r*12+j]
    __shared__ ulonglong2 sLUT[12];    // distinct weights, m=(j*k)%12 (row 1)
    __shared__ u64 sX[NPAIR][PITCH];   // [pair][j*12+c] f32x2 (lo=2p, hi=2p+1)

    const int t = threadIdx.x;

    // ---- weight prep ----
    if (t < 144) {
        float qa = rintf(wr[t] * 65535.0f) * (1.0f / 65536.0f);
        float qb = rintf(wi[t] * 65535.0f) * (1.0f / 65536.0f);
        ulonglong2 w; w.x = pk2(qa, qa); w.y = pk2(qb, qb);
        sWA[t] = w;
    }
    if (t < 12) {
        float qa = rintf(wr[12 + t] * 65535.0f) * (1.0f / 65536.0f);
        float qb = rintf(wi[12 + t] * 65535.0f) * (1.0f / 65536.0f);
        ulonglong2 w; w.x = pk2(qa, qa); w.y = pk2(qb, qb);
        sLUT[t] = w;
    }

    // ---- stage-in 64 tiles: 1152 pair-sets (2 float4 each), 6/thread ----
    const long base4 = (long)blockIdx.x * NPAIR * 72;   // float4 index
    const long n4 = ((long)size * 144) >> 2;
    const float4* in4 = reinterpret_cast<const float4*>(x);
#pragma unroll
    for (int s = 0; s < 6; s++) {
        int p = s * NTHR + t;             // 0..1343 (guard p<1152)
        int pair = p / 36, q = p % 36;
        long i0 = base4 + (long)pair * 72 + q;
        if (p < NPAIR * 36 && i0 + 36 < n4) {
            float4 v0 = in4[i0];
            float4 v1 = in4[i0 + 36];
            ulonglong2* dst = reinterpret_cast<ulonglong2*>(&sX[pair][q * 4]);
            ulonglong2 d0, d1;
            d0.x = pk2(v0.x, v1.x); d0.y = pk2(v0.y, v1.y);
            d1.x = pk2(v0.z, v1.z); d1.y = pk2(v0.w, v1.w);
            dst[0] = d0; dst[1] = d1;
        }
    }
    __syncthreads();

    const int pr = t / NROW;   // tile pair 0..31 (warp spans ~5 values)
    const int r  = t % NROW;   // output row 0..6
    const u64* xp = sX[pr];

    // ---- stage A: rt[c] = sum_j w[r][j]*x[j][c] ----
    u64 rt[12], it[12];
    {
        ulonglong2 w0 = sWA[r * 12];
        const ulonglong2* xr = reinterpret_cast<const ulonglong2*>(xp);
        ulonglong2 x0 = xr[0], x1 = xr[1], x2 = xr[2],
                   x3 = xr[3], x4 = xr[4], x5 = xr[5];
        u64 xv[12] = { x0.x, x0.y, x1.x, x1.y, x2.x, x2.y,
                       x3.x, x3.y, x4.x, x4.y, x5.x, x5.y };
#pragma unroll
        for (int c = 0; c < 12; c++) {
            rt[c] = mul2(w0.x, xv[c]);
            it[c] = mul2(w0.y, xv[c]);
        }
    }
#pragma unroll
    for (int j = 1; j < 12; j++) {
        ulonglong2 w = sWA[r * 12 + j];
        const ulonglong2* xr = reinterpret_cast<const ulonglong2*>(xp + j * 12);
        ulonglong2 x0 = xr[0], x1 = xr[1], x2 = xr[2],
                   x3 = xr[3], x4 = xr[4], x5 = xr[5];
        u64 xv[12] = { x0.x, x0.y, x1.x, x1.y, x2.x, x2.y,
                       x3.x, x3.y, x4.x, x4.y, x5.x, x5.y };
#pragma unroll
        for (int c = 0; c < 12; c++) {
            rt[c] = fma2(w.x, xv[c], rt[c]);
            it[c] = fma2(w.y, xv[c], it[c]);
        }
    }

    // ---- stage-B weights in registers: wre even in m -> 7 regs; wim 12 ----
    u64 wre[7], wim[12];
#pragma unroll
    for (int m = 0; m < 12; m++) {
        ulonglong2 w = sLUT[m];            // full-warp broadcast
        if (m < 7) wre[m] = w.x;
        wim[m] = w.y;
    }

    // k/(12-k) paired sums for the wre dot products
    u64 rs[6], is[6];
#pragma unroll
    for (int k = 1; k <= 5; k++) {
        rs[k] = add2(rt[k], rt[12 - k]);
        is[k] = add2(it[k], it[12 - k]);
    }

    // ---- stage B ----
    float lo[12], hi[12];
#pragma unroll
    for (int c = 0; c < 12; c++) {
        const int m6 = (6 * c) % 12;                 // 0 or 6
        u64 p1 = mul2(rt[0], wre[0]);
        u64 p4 = mul2(it[0], wre[0]);
        p1 = fma2(rt[6], wre[m6 == 6 ? 6 : 0], p1);
        p4 = fma2(it[6], wre[m6 == 6 ? 6 : 0], p4);
#pragma unroll
        for (int k = 1; k <= 5; k++) {
            const int mk = (k * c) % 12;
            const int mm = (mk <= 6) ? mk : 12 - mk; // compile-time
            p1 = fma2(rs[k], wre[mm], p1);
            p4 = fma2(is[k], wre[mm], p4);
        }
        u64 p2 = mul2(it[0], wim[0]);
        u64 p3 = mul2(rt[0], wim[0]);
#pragma unroll
        for (int k = 1; k < 12; k++) {
            const int mk = (k * c) % 12;
            p2 = fma2(it[k], wim[mk], p2);
            p3 = fma2(rt[k], wim[mk], p3);
        }
        u64 ro = add2(p1, neg2(p2));
        u64 io = add2(p3, p4);
        u64 mg = fma2(ro, ro, mul2(io, io));
        float mlo, mhi; upk2(mg, mlo, mhi);
        lo[c] = sqrt_ap(mlo);
        hi[c] = sqrt_ap(mhi);
    }

    // ---- stores: row r, and (for r=1..5) mirrored row 12-r ----
    long item0 = (long)blockIdx.x * NPAIR * 2 + 2 * pr;
    float* tb0 = out + item0 * 144;
    float* tb1 = tb0 + 144;
    const bool full = (item0 + 1 < (long)size);
    const bool mir = (r >= 1);                       // r in 1..5? r<=5 always
    const int  r2 = 12 - r;                          // mirror row (r>=1)

    if (full) {
        float4* o0 = reinterpret_cast<float4*>(tb0 + r * 12);
        float4* o1 = reinterpret_cast<float4*>(tb1 + r * 12);
        o0[0] = make_float4(lo[0], lo[1], lo[2],  lo[3]);
        o0[1] = make_float4(lo[4], lo[5], lo[6],  lo[7]);
        o0[2] = make_float4(lo[8], lo[9], lo[10], lo[11]);
        o1[0] = make_float4(hi[0], hi[1], hi[2],  hi[3]);
        o1[1] = make_float4(hi[4], hi[5], hi[6],  hi[7]);
        o1[2] = make_float4(hi[8], hi[9], hi[10], hi[11]);
        if (mir && r != 6) {
            float4* m0 = reinterpret_cast<float4*>(tb0 + r2 * 12);
            float4* m1 = reinterpret_cast<float4*>(tb1 + r2 * 12);
            m0[0] = make_float4(lo[0], lo[11], lo[10], lo[9]);
            m0[1] = make_float4(lo[8], lo[7],  lo[6],  lo[5]);
            m0[2] = make_float4(lo[4], lo[3],  lo[2],  lo[1]);
            m1[0] = make_float4(hi[0], hi[11], hi[10], hi[9]);
            m1[1] = make_float4(hi[8], hi[7],  hi[6],  hi[5]);
            m1[2] = make_float4(hi[4], hi[3],  hi[2],  hi[1]);
        }
    } else if (item0 < (long)size) {       // odd tail (unused at size=100000)
        float* o0 = tb0 + r * 12;
#pragma unroll
        for (int c = 0; c < 12; c++) o0[c] = lo[c];
        if (mir && r != 6) {
            float* m0 = tb0 + r2 * 12;
            m0[0] = lo[0];
#pragma unroll
            for (int c = 1; c < 12; c++) m0[c] = lo[12 - c];
        }
    }
}

extern "C" void kernel_launch(void* const* d_in, const int* in_sizes, int n_in,
                              void* d_out, int out_size)
{
    const float* x  = (const float*)d_in[0];
    const float* wr = (const float*)d_in[1];
    const float* wi = (const float*)d_in[2];
    float* out = (float*)d_out;

    int size = in_sizes[0] / 144;                        // tiles (100000)
    int blocks = (size + NPAIR * 2 - 1) / (NPAIR * 2);   // 1563
    dft_mag_kernel<<<blocks, NTHR>>>(x, wr, wi, out, size);
}

// round 6
// speedup vs baseline: 5.3753x; 1.1845x over previous
#include <cuda_runtime.h>

// Batched 12x12 complex-DFT magnitude, approx pass only.
// R6: stage-B uses sum/diff folding on BOTH real (even, exact) and imag
// (odd, exact up to the 1e-5 offset ~1.5e-5/term) weight symmetry:
// all four dot products are 7-term. LUT = wre[0..6], wim[0..6] in regs.
// Hermitian output mirror (rows 7..11 = reversed cols of rows 5..1).
// f32x2: 2 tiles per lane. 224 thr = 32 pairs x 7 rows; 3 blocks/SM target.

typedef unsigned long long u64;

__device__ __forceinline__ u64 pk2(float lo, float hi) {
    u64 r; asm("mov.b64 %0,{%1,%2};" : "=l"(r) : "f"(lo), "f"(hi)); return r;
}
__device__ __forceinline__ void upk2(u64 v, float& lo, float& hi) {
    asm("mov.b64 {%0,%1},%2;" : "=f"(lo), "=f"(hi) : "l"(v));
}
__device__ __forceinline__ u64 fma2(u64 a, u64 b, u64 c) {
    u64 d; asm("fma.rn.f32x2 %0,%1,%2,%3;" : "=l"(d) : "l"(a), "l"(b), "l"(c)); return d;
}
__device__ __forceinline__ u64 add2(u64 a, u64 b) {
    u64 d; asm("add.rn.f32x2 %0,%1,%2;" : "=l"(d) : "l"(a), "l"(b)); return d;
}
__device__ __forceinline__ u64 mul2(u64 a, u64 b) {
    u64 d; asm("mul.rn.f32x2 %0,%1,%2;" : "=l"(d) : "l"(a), "l"(b)); return d;
}
__device__ __forceinline__ u64 neg2(u64 a) { return a ^ 0x8000000080000000ULL; }
__device__ __forceinline__ u64 sub2(u64 a, u64 b) { return add2(a, neg2(b)); }
__device__ __forceinline__ float sqrt_ap(float x) {
    float r; asm("sqrt.approx.f32 %0,%1;" : "=f"(r) : "f"(x)); return r;
}

#define PITCH 146
#define NPAIR 32
#define NROW  7
#define NTHR  224

__global__ void __launch_bounds__(NTHR, 3)
dft_mag_kernel(const float* __restrict__ x,
               const float* __restrict__ wr,
               const float* __restrict__ wi,
               float* __restrict__ out, int size)
{
    __shared__ ulonglong2 sWA[144];    // exact stage-A weights [r*12+j]
    __shared__ ulonglong2 sLUT[12];    // distinct weights by m=(jk)%12 (row 1)
    __shared__ u64 sX[NPAIR][PITCH];   // [pair][j*12+c] f32x2

    const int t = threadIdx.x;

    if (t < 144) {
        float qa = rintf(wr[t] * 65535.0f) * (1.0f / 65536.0f);
        float qb = rintf(wi[t] * 65535.0f) * (1.0f / 65536.0f);
        ulonglong2 w; w.x = pk2(qa, qa); w.y = pk2(qb, qb);
        sWA[t] = w;
    }
    if (t < 12) {
        float qa = rintf(wr[12 + t] * 65535.0f) * (1.0f / 65536.0f);
        float qb = rintf(wi[12 + t] * 65535.0f) * (1.0f / 65536.0f);
        ulonglong2 w; w.x = pk2(qa, qa); w.y = pk2(qb, qb);
        sLUT[t] = w;
    }

    // ---- stage-in 64 tiles ----
    const long base4 = (long)blockIdx.x * NPAIR * 72;
    const long n4 = ((long)size * 144) >> 2;
    const float4* in4 = reinterpret_cast<const float4*>(x);
#pragma unroll
    for (int s = 0; s < 6; s++) {
        int p = s * NTHR + t;
        int pair = p / 36, q = p % 36;
        long i0 = base4 + (long)pair * 72 + q;
        if (p < NPAIR * 36 && i0 + 36 < n4) {
            float4 v0 = in4[i0];
            float4 v1 = in4[i0 + 36];
            ulonglong2* dst = reinterpret_cast<ulonglong2*>(&sX[pair][q * 4]);
            ulonglong2 d0, d1;
            d0.x = pk2(v0.x, v1.x); d0.y = pk2(v0.y, v1.y);
            d1.x = pk2(v0.z, v1.z); d1.y = pk2(v0.w, v1.w);
            dst[0] = d0; dst[1] = d1;
        }
    }
    __syncthreads();

    const int pr = t / NROW;
    const int r  = t % NROW;
    const u64* xp = sX[pr];

    // ---- stage A: rt[c] = sum_j w[r][j]*x[j][c] (exact entries) ----
    u64 rt[12], it[12];
    {
        ulonglong2 w0 = sWA[r * 12];
        const ulonglong2* xr = reinterpret_cast<const ulonglong2*>(xp);
        ulonglong2 x0 = xr[0], x1 = xr[1], x2 = xr[2],
                   x3 = xr[3], x4 = xr[4], x5 = xr[5];
        u64 xv[12] = { x0.x, x0.y, x1.x, x1.y, x2.x, x2.y,
                       x3.x, x3.y, x4.x, x4.y, x5.x, x5.y };
#pragma unroll
        for (int c = 0; c < 12; c++) {
            rt[c] = mul2(w0.x, xv[c]);
            it[c] = mul2(w0.y, xv[c]);
        }
    }
#pragma unroll
    for (int j = 1; j < 12; j++) {
        ulonglong2 w = sWA[r * 12 + j];
        const ulonglong2* xr = reinterpret_cast<const ulonglong2*>(xp + j * 12);
        ulonglong2 x0 = xr[0], x1 = xr[1], x2 = xr[2],
                   x3 = xr[3], x4 = xr[4], x5 = xr[5];
        u64 xv[12] = { x0.x, x0.y, x1.x, x1.y, x2.x, x2.y,
                       x3.x, x3.y, x4.x, x4.y, x5.x, x5.y };
#pragma unroll
        for (int c = 0; c < 12; c++) {
            rt[c] = fma2(w.x, xv[c], rt[c]);
            it[c] = fma2(w.y, xv[c], it[c]);
        }
    }

    // ---- fold k/(12-k): sums (for even wre) and diffs (for odd wim) ----
    u64 rs[6], rd[6], is[6], id[6];
#pragma unroll
    for (int k = 1; k <= 5; k++) {
        rs[k] = add2(rt[k], rt[12 - k]);
        rd[k] = sub2(rt[k], rt[12 - k]);
        is[k] = add2(it[k], it[12 - k]);
        id[k] = sub2(it[k], it[12 - k]);
    }
    const u64 a0 = rt[0], a6 = rt[6], b0 = it[0], b6 = it[6];

    // ---- register LUT: wre[m], wim[m], m = 0..6 ----
    u64 wre[7], wim[7];
#pragma unroll
    for (int m = 0; m < 7; m++) {
        ulonglong2 w = sLUT[m];
        wre[m] = w.x; wim[m] = w.y;
    }

    // ---- stage B: 7-term dot products via symmetry ----
    float lo[12], hi[12];
#pragma unroll
    for (int c = 0; c < 12; c++) {
        const int m6 = ((6 * c) % 12 == 6) ? 6 : 0;      // compile-time
        // p1 = rt @ wre  (even)
        u64 p1 = fma2(a6, wre[m6], mul2(a0, wre[0]));
        u64 p4 = fma2(b6, wre[m6], mul2(b0, wre[0]));
        // p2 = it @ wim, p3 = rt @ wim (odd): pos/neg accumulators
        u64 p2p = fma2(b6, wim[m6], mul2(b0, wim[0]));
        u64 p2n = 0;
        u64 p3p = fma2(a6, wim[m6], mul2(a0, wim[0]));
        u64 p3n = 0;
#pragma unroll
        for (int k = 1; k <= 5; k++) {
            const int mk = (k * c) % 12;                 // compile-time
            const int me = (mk <= 6) ? mk : 12 - mk;
            p1 = fma2(rs[k], wre[me], p1);
            p4 = fma2(is[k], wre[me], p4);
            if (mk == 0 || mk == 6) {
                p2p = fma2(is[k], wim[mk], p2p);
                p3p = fma2(rs[k], wim[mk], p3p);
            } else if (mk < 6) {
                p2p = fma2(id[k], wim[mk], p2p);
                p3p = fma2(rd[k], wim[mk], p3p);
            } else {
                p2n = fma2(id[k], wim[12 - mk], p2n);
                p3n = fma2(rd[k], wim[12 - mk], p3n);
            }
        }
        u64 ro = add2(sub2(p1, p2p), p2n);
        u64 io = add2(sub2(p3p, p3n), p4);
        u64 mg = fma2(ro, ro, mul2(io, io));
        float mlo, mhi; upk2(mg, mlo, mhi);
        lo[c] = sqrt_ap(mlo);
        hi[c] = sqrt_ap(mhi);
    }

    // ---- stores: row r + (r=1..5) Hermitian mirror row 12-r ----
    long item0 = (long)blockIdx.x * NPAIR * 2 + 2 * pr;
    float* tb0 = out + item0 * 144;
    float* tb1 = tb0 + 144;
    const bool full = (item0 + 1 < (long)size);
    const int  r2 = 12 - r;

    if (full) {
        float4* o0 = reinterpret_cast<float4*>(tb0 + r * 12);
        float4* o1 = reinterpret_cast<float4*>(tb1 + r * 12);
        o0[0] = make_float4(lo[0], lo[1], lo[2],  lo[3]);
        o0[1] = make_float4(lo[4], lo[5], lo[6],  lo[7]);
        o0[2] = make_float4(lo[8], lo[9], lo[10], lo[11]);
        o1[0] = make_float4(hi[0], hi[1], hi[2],  hi[3]);
        o1[1] = make_float4(hi[4], hi[5], hi[6],  hi[7]);
        o1[2] = make_float4(hi[8], hi[9], hi[10], hi[11]);
        if (r >= 1 && r <= 5) {
            float4* m0 = reinterpret_cast<float4*>(tb0 + r2 * 12);
            float4* m1 = reinterpret_cast<float4*>(tb1 + r2 * 12);
            m0[0] = make_float4(lo[0], lo[11], lo[10], lo[9]);
            m0[1] = make_float4(lo[8], lo[7],  lo[6],  lo[5]);
            m0[2] = make_float4(lo[4], lo[3],  lo[2],  lo[1]);
            m1[0] = make_float4(hi[0], hi[11], hi[10], hi[9]);
            m1[1] = make_float4(hi[8], hi[7],  hi[6],  hi[5]);
            m1[2] = make_float4(hi[4], hi[3],  hi[2],  hi[1]);
        }
    } else if (item0 < (long)size) {       // odd tail (unused at size=100000)
        float* o0 = tb0 + r * 12;
#pragma unroll
        for (int c = 0; c < 12; c++) o0[c] = lo[c];
        if (r >= 1 && r <= 5) {
            float* m0 = tb0 + r2 * 12;
            m0[0] = lo[0];
#pragma unroll
            for (int c = 1; c < 12; c++) m0[c] = lo[12 - c];
        }
    }
}

extern "C" void kernel_launch(void* const* d_in, const int* in_sizes, int n_in,
                              void* d_out, int out_size)
{
    const float* x  = (const float*)d_in[0];
    const float* wr = (const float*)d_in[1];
    const float* wi = (const float*)d_in[2];
    float* out = (float*)d_out;

    int size = in_sizes[0] / 144;
    int blocks = (size + NPAIR * 2 - 1) / (NPAIR * 2);   // 1563
    dft_mag_kernel<<<blocks, NTHR>>>(x, wr, wi, out, size);
}